// round 12
// baseline (speedup 1.0000x reference)
#include <cuda_runtime.h>
#include <cuda_bf16.h>
#include <cuda_fp16.h>
#include <cstdint>

#define NN   50000
#define EE   800000
#define DH   128

// ---------------- device scratch ----------
__device__ int    g_is64;
__device__ int    g_src[EE];
__device__ int    g_dst[EE];
__device__ int    g_cnt[NN];
__device__ int    g_off[NN];
__device__ int    g_pos[NN];
__device__ float  g_dinv[NN];
__device__ int2   g_edge[EE];       // {src, norm bits} per CSR slot
__device__ __half g_xwh[NN * DH];   // GEMM output, fp16 (gather payload)
__device__ float  g_h [NN * DH];    // layer feature buffer (fp32)

// ---------------- zero + dtype detection (fused) ----------------
__global__ void k_dz(const void* ei) {
    int i = blockIdx.x * blockDim.x + threadIdx.x;
    if (i < NN) { g_cnt[i] = 0; g_pos[i] = 0; }
    if (i == 0) {
        const unsigned* p = (const unsigned*)ei;
        int is64 = 1;
        for (int q = 0; q < 64; q++)
            if (p[2 * q + 1] != 0u) { is64 = 0; break; }
        g_is64 = is64;
    }
}

__global__ void k_convert_count(const void* ei) {
    int e = blockIdx.x * blockDim.x + threadIdx.x;
    if (e >= EE) return;
    int s, d;
    if (g_is64) {
        const long long* p = (const long long*)ei;
        s = (int)p[e]; d = (int)p[EE + e];
    } else {
        const int* p = (const int*)ei;
        s = p[e]; d = p[EE + e];
    }
    g_src[e] = s; g_dst[e] = d;
    atomicAdd(&g_cnt[d], 1);
}

// single-block exclusive scan (shfl-based) + dinv (fused)
__global__ void k_scan() {
    __shared__ int wsum[32];
    const int C = (NN + 1023) / 1024;
    int t = threadIdx.x, lane = t & 31, wid = t >> 5;
    int beg = t * C;
    int end = min(beg + C, NN);
    int s = 0;
    for (int i = beg; i < end; i++) s += g_cnt[i];
    int v = s;
    #pragma unroll
    for (int d = 1; d < 32; d <<= 1) {
        int u = __shfl_up_sync(0xFFFFFFFFu, v, d);
        if (lane >= d) v += u;
    }
    if (lane == 31) wsum[wid] = v;
    __syncthreads();
    if (wid == 0) {
        int w = wsum[lane];
        #pragma unroll
        for (int d = 1; d < 32; d <<= 1) {
            int u = __shfl_up_sync(0xFFFFFFFFu, w, d);
            if (lane >= d) w += u;
        }
        wsum[lane] = w;
    }
    __syncthreads();
    int run = v - s + (wid ? wsum[wid - 1] : 0);
    for (int i = beg; i < end; i++) {
        int c = g_cnt[i];
        g_off[i] = run;
        g_dinv[i] = rsqrtf((float)c + 1.0f);
        run += c;
    }
}

__global__ void k_scatter() {
    int e = blockIdx.x * blockDim.x + threadIdx.x;
    if (e >= EE) return;
    int s = g_src[e];
    int d = g_dst[e];
    int p = g_off[d] + atomicAdd(&g_pos[d], 1);
    g_edge[p] = make_int2(s, __float_as_int(g_dinv[s] * g_dinv[d]));
}

// ---------------- bf16x3 mma GEMM: g_xwh = fp16( A @ W ) ----------------
// CTA tile 128x128, K=128 resident. 256 threads = 8 warps (2x4 warp grid,
// warp tile 64x32). Rows padded to 272B for conflict-free fragment LDS.
// W is split to bf16 hi/lo + transposed inline (W stays L2-resident).
#define ROWB 272
#define SM_AH 0
#define SM_AL (SM_AH + 128 * ROWB)
#define SM_BH (SM_AL + 128 * ROWB)
#define SM_BL (SM_BH + 128 * ROWB)
#define SM_GEMM_TOTAL (SM_BL + 128 * ROWB)   // 139264 B

__device__ __forceinline__ void mma_bf16(float* d, uint32_t a0, uint32_t a1,
                                         uint32_t a2, uint32_t a3,
                                         uint32_t b0, uint32_t b1) {
    asm volatile(
        "mma.sync.aligned.m16n8k16.row.col.f32.bf16.bf16.f32 "
        "{%0,%1,%2,%3}, {%4,%5,%6,%7}, {%8,%9}, {%0,%1,%2,%3};"
        : "+f"(d[0]), "+f"(d[1]), "+f"(d[2]), "+f"(d[3])
        : "r"(a0), "r"(a1), "r"(a2), "r"(a3), "r"(b0), "r"(b1));
}

__device__ __forceinline__ uint32_t bsplit_hi(float x, float& rem) {
    __nv_bfloat16 hb = __float2bfloat16_rn(x);
    rem = x - __bfloat162float(hb);
    return (uint32_t)__bfloat16_as_ushort(hb);
}

__global__ __launch_bounds__(256) void k_gemm_mma(const float* __restrict__ A_in,
                                                  const float* __restrict__ W) {
    const float* A = A_in ? A_in : (const float*)g_h;
    extern __shared__ char sm[];
    int tid  = threadIdx.x;
    int wid  = tid >> 5;
    int lane = tid & 31;
    int r0   = blockIdx.x * 128;

    // ---- load A: fp32 -> bf16 hi/lo, row-major [128][128] padded ----
    {
        int r  = tid >> 1;
        int c0 = (tid & 1) * 64;
        bool valid = (r0 + r) < NN;
        const float4* src = (const float4*)(A + (size_t)(r0 + r) * DH + c0);
        char* dh = sm + SM_AH + r * ROWB + c0 * 2;
        char* dl = sm + SM_AL + r * ROWB + c0 * 2;
        #pragma unroll
        for (int i = 0; i < 16; i++) {
            float4 v = valid ? src[i] : make_float4(0.f, 0.f, 0.f, 0.f);
            float rx, ry, rz, rw;
            uint32_t hx = bsplit_hi(v.x, rx), hy = bsplit_hi(v.y, ry);
            uint32_t hz = bsplit_hi(v.z, rz), hw = bsplit_hi(v.w, rw);
            uint32_t h01 = hx | (hy << 16);
            uint32_t h23 = hz | (hw << 16);
            float d0, d1, d2, d3;
            uint32_t lx = bsplit_hi(rx, d0), ly = bsplit_hi(ry, d1);
            uint32_t lz = bsplit_hi(rz, d2), lw = bsplit_hi(rw, d3);
            uint32_t l01 = lx | (ly << 16);
            uint32_t l23 = lz | (lw << 16);
            *(uint2*)(dh + i * 8) = make_uint2(h01, h23);
            *(uint2*)(dl + i * 8) = make_uint2(l01, l23);
        }
    }
    // ---- load B: W[k][n] fp32 -> transpose + bf16 hi/lo split inline ----
    {
        int n  = tid >> 1;
        int c0 = (tid & 1) * 64;
        char* dh = sm + SM_BH + n * ROWB + c0 * 2;
        char* dl = sm + SM_BL + n * ROWB + c0 * 2;
        #pragma unroll
        for (int i = 0; i < 64; i += 2) {
            float v0 = W[(size_t)(c0 + i) * DH + n];
            float v1 = W[(size_t)(c0 + i + 1) * DH + n];
            float r0f, r1f, z;
            uint32_t h0 = bsplit_hi(v0, r0f), h1 = bsplit_hi(v1, r1f);
            uint32_t l0 = bsplit_hi(r0f, z),  l1 = bsplit_hi(r1f, z);
            *(uint32_t*)(dh + i * 2) = h0 | (h1 << 16);
            *(uint32_t*)(dl + i * 2) = l0 | (l1 << 16);
        }
    }
    __syncthreads();

    // warp grid: wm = wid & 1 (2 x 64 rows), wn = wid >> 1 (4 x 32 cols)
    int wm = (wid & 1) * 64;
    int wn = (wid >> 1) * 32;
    int g  = lane >> 2;      // 0..7
    int t  = lane & 3;       // 0..3

    float acc[4][4][4];      // [mt][nt][4]
    #pragma unroll
    for (int mt = 0; mt < 4; mt++)
        #pragma unroll
        for (int nt = 0; nt < 4; nt++)
            #pragma unroll
            for (int q = 0; q < 4; q++) acc[mt][nt][q] = 0.0f;

    #pragma unroll
    for (int ks = 0; ks < 8; ks++) {
        int kb = ks * 32;    // byte offset of k-chunk (16 elems * 2B)
        uint32_t bh[4][2], bl[4][2];
        #pragma unroll
        for (int nt = 0; nt < 4; nt++) {
            int nrow = wn + nt * 8 + g;
            const char* ph = sm + SM_BH + nrow * ROWB + kb + t * 4;
            const char* pl = sm + SM_BL + nrow * ROWB + kb + t * 4;
            bh[nt][0] = *(const uint32_t*)(ph);
            bh[nt][1] = *(const uint32_t*)(ph + 16);
            bl[nt][0] = *(const uint32_t*)(pl);
            bl[nt][1] = *(const uint32_t*)(pl + 16);
        }
        #pragma unroll
        for (int mt = 0; mt < 4; mt++) {
            int mrow = wm + mt * 16 + g;
            const char* ph = sm + SM_AH + mrow * ROWB + kb + t * 4;
            const char* pl = sm + SM_AL + mrow * ROWB + kb + t * 4;
            uint32_t ah0 = *(const uint32_t*)(ph);
            uint32_t ah1 = *(const uint32_t*)(ph + 8 * ROWB);
            uint32_t ah2 = *(const uint32_t*)(ph + 16);
            uint32_t ah3 = *(const uint32_t*)(ph + 8 * ROWB + 16);
            uint32_t al0 = *(const uint32_t*)(pl);
            uint32_t al1 = *(const uint32_t*)(pl + 8 * ROWB);
            uint32_t al2 = *(const uint32_t*)(pl + 16);
            uint32_t al3 = *(const uint32_t*)(pl + 8 * ROWB + 16);
            #pragma unroll
            for (int nt = 0; nt < 4; nt++) {
                mma_bf16(acc[mt][nt], ah0, ah1, ah2, ah3, bh[nt][0], bh[nt][1]);
                mma_bf16(acc[mt][nt], ah0, ah1, ah2, ah3, bl[nt][0], bl[nt][1]);
                mma_bf16(acc[mt][nt], al0, al1, al2, al3, bh[nt][0], bh[nt][1]);
            }
        }
    }

    // ---- epilogue: write D as fp16 to g_xwh ----
    #pragma unroll
    for (int mt = 0; mt < 4; mt++) {
        int row = r0 + wm + mt * 16 + g;
        #pragma unroll
        for (int nt = 0; nt < 4; nt++) {
            int col = wn + nt * 8 + t * 2;
            if (row < NN) {
                __half2 p = __floats2half2_rn(acc[mt][nt][0], acc[mt][nt][1]);
                *(uint32_t*)((char*)g_xwh + ((size_t)row * DH + col) * 2) =
                    *(uint32_t*)&p;
            }
            if (row + 8 < NN) {
                __half2 p = __floats2half2_rn(acc[mt][nt][2], acc[mt][nt][3]);
                *(uint32_t*)((char*)g_xwh + ((size_t)(row + 8) * DH + col) * 2) =
                    *(uint32_t*)&p;
            }
        }
    }
}

// ---------------- aggregation: g_h = relu( Ahat @ xw + b ) --------------
// one warp per node; HALF-warp per feature row: lane = (half, c8),
// half = lane>>4 processes edges j+half; c8 = lane&15 covers cols
// [c8*8, c8*8+8) as one uint4 (8 halves, 16B). 2x unroll -> 4 independent
// 16B gathers in flight per warp. Cross-half combine via shfl_xor(16).
// Last layer fuses the FC head (dot with Wfc, + bfc) directly to out.
__global__ __launch_bounds__(256) void k_agg(const float* __restrict__ b,
                                             const float* __restrict__ Wfc,
                                             const float* __restrict__ bfc,
                                             float* __restrict__ out) {
    int warp = (blockIdx.x * blockDim.x + threadIdx.x) >> 5;
    int lane = threadIdx.x & 31;
    if (warp >= NN) return;
    int node = warp;
    int half = lane >> 4;
    int c8   = lane & 15;

    const uint4* xw = (const uint4*)g_xwh;   // 16 uint4 per 128-col row

    float acc[8];
    // self term (half 0 only; half 1 contributes 0)
    {
        float dv = g_dinv[node];
        float self = (half == 0) ? dv * dv : 0.0f;
        uint4 r = xw[node * 16 + c8];
        const __half2* h2 = (const __half2*)&r;
        #pragma unroll
        for (int q = 0; q < 4; q++) {
            float2 f = __half22float2(h2[q]);
            acc[2 * q]     = f.x * self;
            acc[2 * q + 1] = f.y * self;
        }
    }

    int start = g_off[node];
    int m     = g_cnt[node];

    for (int j = 0; j < m; j += 4) {
        int e0 = j + half;
        int e1 = j + 2 + half;
        int2 ed0 = (e0 < m) ? g_edge[start + e0] : make_int2(0, 0);
        int2 ed1 = (e1 < m) ? g_edge[start + e1] : make_int2(0, 0);
        uint4 r0 = xw[(size_t)ed0.x * 16 + c8];
        uint4 r1 = xw[(size_t)ed1.x * 16 + c8];
        float n0 = __int_as_float(ed0.y);
        float n1 = __int_as_float(ed1.y);
        const __half2* a2 = (const __half2*)&r0;
        const __half2* b2 = (const __half2*)&r1;
        #pragma unroll
        for (int q = 0; q < 4; q++) {
            float2 fa = __half22float2(a2[q]);
            float2 fb = __half22float2(b2[q]);
            acc[2 * q]     += fa.x * n0 + fb.x * n1;
            acc[2 * q + 1] += fa.y * n0 + fb.y * n1;
        }
    }

    // combine the two halves: lane L and L^16 hold same cols, disjoint edges
    #pragma unroll
    for (int q = 0; q < 8; q++)
        acc[q] += __shfl_xor_sync(0xFFFFFFFFu, acc[q], 16);

    // bias + relu (each lane: 8 cols at c8*8)
    {
        const float4* b4 = (const float4*)(b + c8 * 8);
        float4 bb0 = b4[0], bb1 = b4[1];
        acc[0] = fmaxf(acc[0] + bb0.x, 0.0f);
        acc[1] = fmaxf(acc[1] + bb0.y, 0.0f);
        acc[2] = fmaxf(acc[2] + bb0.z, 0.0f);
        acc[3] = fmaxf(acc[3] + bb0.w, 0.0f);
        acc[4] = fmaxf(acc[4] + bb1.x, 0.0f);
        acc[5] = fmaxf(acc[5] + bb1.y, 0.0f);
        acc[6] = fmaxf(acc[6] + bb1.z, 0.0f);
        acc[7] = fmaxf(acc[7] + bb1.w, 0.0f);
    }

    if (Wfc) {
        const float4* w4 = (const float4*)(Wfc + c8 * 8);
        float4 w0 = w4[0], w1 = w4[1];
        float sum = acc[0] * w0.x + acc[1] * w0.y + acc[2] * w0.z + acc[3] * w0.w
                  + acc[4] * w1.x + acc[5] * w1.y + acc[6] * w1.z + acc[7] * w1.w;
        // both halves hold identical values; reduce the 16 distinct lanes
        #pragma unroll
        for (int d = 8; d > 0; d >>= 1)
            sum += __shfl_xor_sync(0xFFFFFFFFu, sum, d);
        if (lane == 0) out[node] = sum + bfc[0];
    } else if (half == 0) {
        float4* dst = (float4*)(g_h + (size_t)node * DH + c8 * 8);
        dst[0] = make_float4(acc[0], acc[1], acc[2], acc[3]);
        dst[1] = make_float4(acc[4], acc[5], acc[6], acc[7]);
    }
}

// ---------------- launch -------------------------------------------------
extern "C" void kernel_launch(void* const* d_in, const int* in_sizes, int n_in,
                              void* d_out, int out_size) {
    const float* x    = (const float*)d_in[0];
    const void*  ei   = d_in[1];
    const float* W1   = (const float*)d_in[2];
    const float* b1   = (const float*)d_in[3];
    const float* W2   = (const float*)d_in[4];
    const float* b2   = (const float*)d_in[5];
    const float* W3   = (const float*)d_in[6];
    const float* b3   = (const float*)d_in[7];
    const float* Wfc  = (const float*)d_in[8];
    const float* bfc  = (const float*)d_in[9];
    float* out = (float*)d_out;

    static int smem_set = 0;
    if (!smem_set) {
        cudaFuncSetAttribute(k_gemm_mma,
                             cudaFuncAttributeMaxDynamicSharedMemorySize,
                             SM_GEMM_TOTAL);
        smem_set = 1;
    }

    const int TB = 256;
    int ge = (EE + TB - 1) / TB;
    int gn = (NN + TB - 1) / TB;
    int ggemm = (NN + 127) / 128;
    int gwarp = (NN * 32 + TB - 1) / TB;

    k_dz<<<gn, TB>>>(ei);                                    // 1
    k_convert_count<<<ge, TB>>>(ei);                         // 2
    k_scan<<<1, 1024>>>();                                   // 3
    // gemm1 is independent of the CSR build -> launch 4 (profiled slot)
    k_gemm_mma<<<ggemm, 256, SM_GEMM_TOTAL>>>(x, W1);        // 4
    k_scatter<<<ge, TB>>>();                                 // 5
    k_agg<<<gwarp, TB>>>(b1, nullptr, nullptr, nullptr);     // 6
    // layer 2
    k_gemm_mma<<<ggemm, 256, SM_GEMM_TOTAL>>>(nullptr, W2);  // 7
    k_agg<<<gwarp, TB>>>(b2, nullptr, nullptr, nullptr);     // 8
    // layer 3 + fused FC head
    k_gemm_mma<<<ggemm, 256, SM_GEMM_TOTAL>>>(nullptr, W3);  // 9
    k_agg<<<gwarp, TB>>>(b3, Wfc, bfc, out);                 // 10
}

// round 13
// speedup vs baseline: 1.0176x; 1.0176x over previous
#include <cuda_runtime.h>
#include <cuda_bf16.h>
#include <cuda_fp16.h>
#include <cstdint>

#define NN   50000
#define EE   800000
#define DH   128

// ---------------- device scratch ----------
__device__ int    g_is64;
__device__ int    g_src[EE];
__device__ int    g_dst[EE];
__device__ int    g_cnt[NN];
__device__ int    g_off[NN];
__device__ int    g_pos[NN];
__device__ float  g_dinv[NN];
__device__ int2   g_edge[EE];                 // {src, norm bits} per CSR slot
__device__ __half g_xwh[NN * DH];             // GEMM output, fp16 gather payload
__device__ unsigned short g_ah[NN * DH];      // activations, bf16 hi
__device__ unsigned short g_al[NN * DH];      // activations, bf16 lo
__device__ unsigned short g_wh[3 * DH * DH];  // W^T hi per layer, [l][n][k]
__device__ unsigned short g_wl[3 * DH * DH];  // W^T lo per layer

__device__ __forceinline__ uint32_t bsplit_hi(float x, float& rem) {
    __nv_bfloat16 hb = __float2bfloat16_rn(x);
    rem = x - __bfloat162float(hb);
    return (uint32_t)__bfloat16_as_ushort(hb);
}

// ---------------- x -> bf16 hi/lo split (one-shot) ----------------
__global__ void k_splitx(const float* __restrict__ x) {
    int i = blockIdx.x * blockDim.x + threadIdx.x;   // one float4 per thread
    if (i >= NN * DH / 4) return;
    float4 v = ((const float4*)x)[i];
    float rx, ry, rz, rw, z;
    uint32_t hx = bsplit_hi(v.x, rx), hy = bsplit_hi(v.y, ry);
    uint32_t hz = bsplit_hi(v.z, rz), hw = bsplit_hi(v.w, rw);
    uint32_t lx = bsplit_hi(rx, z), ly = bsplit_hi(ry, z);
    uint32_t lz = bsplit_hi(rz, z), lw = bsplit_hi(rw, z);
    ((uint2*)g_ah)[i] = make_uint2(hx | (hy << 16), hz | (hw << 16));
    ((uint2*)g_al)[i] = make_uint2(lx | (ly << 16), lz | (lw << 16));
}

// ---------------- W^T + bf16 split for all 3 layers -------------------
__global__ void k_wprep3(const float* __restrict__ W1,
                         const float* __restrict__ W2,
                         const float* __restrict__ W3) {
    int n = blockIdx.x, l = blockIdx.y, k = threadIdx.x;
    const float* W = (l == 0) ? W1 : (l == 1) ? W2 : W3;
    float v = W[k * DH + n];
    float r;
    uint32_t h = bsplit_hi(v, r);
    uint32_t lo = bsplit_hi(r, v);
    g_wh[l * DH * DH + n * DH + k] = (unsigned short)h;
    g_wl[l * DH * DH + n * DH + k] = (unsigned short)lo;
}

// ---------------- zero + dtype detection (fused) ----------------
__global__ void k_dz(const void* ei) {
    int i = blockIdx.x * blockDim.x + threadIdx.x;
    if (i < NN) { g_cnt[i] = 0; g_pos[i] = 0; }
    if (i == 0) {
        const unsigned* p = (const unsigned*)ei;
        int is64 = 1;
        for (int q = 0; q < 64; q++)
            if (p[2 * q + 1] != 0u) { is64 = 0; break; }
        g_is64 = is64;
    }
}

__global__ void k_convert_count(const void* ei) {
    int e = blockIdx.x * blockDim.x + threadIdx.x;
    if (e >= EE) return;
    int s, d;
    if (g_is64) {
        const long long* p = (const long long*)ei;
        s = (int)p[e]; d = (int)p[EE + e];
    } else {
        const int* p = (const int*)ei;
        s = p[e]; d = p[EE + e];
    }
    g_src[e] = s; g_dst[e] = d;
    atomicAdd(&g_cnt[d], 1);
}

// single-block exclusive scan (shfl-based) + dinv (fused)
__global__ void k_scan() {
    __shared__ int wsum[32];
    const int C = (NN + 1023) / 1024;
    int t = threadIdx.x, lane = t & 31, wid = t >> 5;
    int beg = t * C;
    int end = min(beg + C, NN);
    int s = 0;
    for (int i = beg; i < end; i++) s += g_cnt[i];
    int v = s;
    #pragma unroll
    for (int d = 1; d < 32; d <<= 1) {
        int u = __shfl_up_sync(0xFFFFFFFFu, v, d);
        if (lane >= d) v += u;
    }
    if (lane == 31) wsum[wid] = v;
    __syncthreads();
    if (wid == 0) {
        int w = wsum[lane];
        #pragma unroll
        for (int d = 1; d < 32; d <<= 1) {
            int u = __shfl_up_sync(0xFFFFFFFFu, w, d);
            if (lane >= d) w += u;
        }
        wsum[lane] = w;
    }
    __syncthreads();
    int run = v - s + (wid ? wsum[wid - 1] : 0);
    for (int i = beg; i < end; i++) {
        int c = g_cnt[i];
        g_off[i] = run;
        g_dinv[i] = rsqrtf((float)c + 1.0f);
        run += c;
    }
}

__global__ void k_scatter() {
    int e = blockIdx.x * blockDim.x + threadIdx.x;
    if (e >= EE) return;
    int s = g_src[e];
    int d = g_dst[e];
    int p = g_off[d] + atomicAdd(&g_pos[d], 1);
    g_edge[p] = make_int2(s, __float_as_int(g_dinv[s] * g_dinv[d]));
}

// ---------------- bf16x3 mma GEMM: g_xwh = fp16( A @ W ) ----------------
// CTA tile 128x128; K in 2 chunks of 64, single-buffered -> 72KB SMEM,
// 2 CTAs/SM. All operands pre-split bf16; prologue is pure copies.
#define ROWB2 144
#define SM2_AH 0
#define SM2_AL (SM2_AH + 128 * ROWB2)
#define SM2_BH (SM2_AL + 128 * ROWB2)
#define SM2_BL (SM2_BH + 128 * ROWB2)
#define SM2_TOTAL (SM2_BL + 128 * ROWB2)   // 73728 B

__device__ __forceinline__ void mma_bf16(float* d, uint32_t a0, uint32_t a1,
                                         uint32_t a2, uint32_t a3,
                                         uint32_t b0, uint32_t b1) {
    asm volatile(
        "mma.sync.aligned.m16n8k16.row.col.f32.bf16.bf16.f32 "
        "{%0,%1,%2,%3}, {%4,%5,%6,%7}, {%8,%9}, {%0,%1,%2,%3};"
        : "+f"(d[0]), "+f"(d[1]), "+f"(d[2]), "+f"(d[3])
        : "r"(a0), "r"(a1), "r"(a2), "r"(a3), "r"(b0), "r"(b1));
}

__global__ __launch_bounds__(256, 2) void k_gemm_mma(int layer) {
    extern __shared__ char sm[];
    int tid  = threadIdx.x;
    int wid  = tid >> 5;
    int lane = tid & 31;
    int r0   = blockIdx.x * 128;

    const unsigned short* WH = g_wh + layer * DH * DH;
    const unsigned short* WL = g_wl + layer * DH * DH;

    // warp grid: wm = wid & 1 (2 x 64 rows), wn = wid >> 1 (4 x 32 cols)
    int wm = (wid & 1) * 64;
    int wn = (wid >> 1) * 32;
    int g  = lane >> 2;      // 0..7
    int t  = lane & 3;       // 0..3

    float acc[4][4][4];
    #pragma unroll
    for (int mt = 0; mt < 4; mt++)
        #pragma unroll
        for (int nt = 0; nt < 4; nt++)
            #pragma unroll
            for (int q = 0; q < 4; q++) acc[mt][nt][q] = 0.0f;

    int cr = tid >> 1;           // copy row (0..127)
    int hf = tid & 1;            // 0/1 half of 64-elem chunk
    int arow = min(r0 + cr, NN - 1);

    #pragma unroll
    for (int kc = 0; kc < 2; kc++) {
        if (kc) __syncthreads();   // all MMA reads of prev chunk done

        // ---- copy tiles (pure uint4 moves, 64B per thread per tile) ----
        {
            size_t aoff = ((size_t)arow * DH + kc * 64 + hf * 32);
            const uint4* sa = (const uint4*)(g_ah + aoff);
            const uint4* sl = (const uint4*)(g_al + aoff);
            uint4* dah = (uint4*)(sm + SM2_AH + cr * ROWB2 + hf * 64);
            uint4* dal = (uint4*)(sm + SM2_AL + cr * ROWB2 + hf * 64);
            #pragma unroll
            for (int i = 0; i < 4; i++) { dah[i] = sa[i]; dal[i] = sl[i]; }

            size_t boff = ((size_t)cr * DH + kc * 64 + hf * 32);
            const uint4* sbh = (const uint4*)(WH + boff);
            const uint4* sbl = (const uint4*)(WL + boff);
            uint4* dbh = (uint4*)(sm + SM2_BH + cr * ROWB2 + hf * 64);
            uint4* dbl = (uint4*)(sm + SM2_BL + cr * ROWB2 + hf * 64);
            #pragma unroll
            for (int i = 0; i < 4; i++) { dbh[i] = sbh[i]; dbl[i] = sbl[i]; }
        }
        __syncthreads();

        // ---- mainloop over this chunk's 4 k-steps ----
        #pragma unroll
        for (int ks = 0; ks < 4; ks++) {
            int kb = ks * 32;
            uint32_t bh[4][2], bl[4][2];
            #pragma unroll
            for (int nt = 0; nt < 4; nt++) {
                int nrow = wn + nt * 8 + g;
                const char* ph = sm + SM2_BH + nrow * ROWB2 + kb + t * 4;
                const char* pl = sm + SM2_BL + nrow * ROWB2 + kb + t * 4;
                bh[nt][0] = *(const uint32_t*)(ph);
                bh[nt][1] = *(const uint32_t*)(ph + 16);
                bl[nt][0] = *(const uint32_t*)(pl);
                bl[nt][1] = *(const uint32_t*)(pl + 16);
            }
            #pragma unroll
            for (int mt = 0; mt < 4; mt++) {
                int mrow = wm + mt * 16 + g;
                const char* ph = sm + SM2_AH + mrow * ROWB2 + kb + t * 4;
                const char* pl = sm + SM2_AL + mrow * ROWB2 + kb + t * 4;
                uint32_t ah0 = *(const uint32_t*)(ph);
                uint32_t ah1 = *(const uint32_t*)(ph + 8 * ROWB2);
                uint32_t ah2 = *(const uint32_t*)(ph + 16);
                uint32_t ah3 = *(const uint32_t*)(ph + 8 * ROWB2 + 16);
                uint32_t al0 = *(const uint32_t*)(pl);
                uint32_t al1 = *(const uint32_t*)(pl + 8 * ROWB2);
                uint32_t al2 = *(const uint32_t*)(pl + 16);
                uint32_t al3 = *(const uint32_t*)(pl + 8 * ROWB2 + 16);
                #pragma unroll
                for (int nt = 0; nt < 4; nt++) {
                    mma_bf16(acc[mt][nt], ah0, ah1, ah2, ah3, bh[nt][0], bh[nt][1]);
                    mma_bf16(acc[mt][nt], ah0, ah1, ah2, ah3, bl[nt][0], bl[nt][1]);
                    mma_bf16(acc[mt][nt], al0, al1, al2, al3, bh[nt][0], bh[nt][1]);
                }
            }
        }
    }

    // ---- epilogue: write D as fp16 to g_xwh ----
    #pragma unroll
    for (int mt = 0; mt < 4; mt++) {
        int row = r0 + wm + mt * 16 + g;
        #pragma unroll
        for (int nt = 0; nt < 4; nt++) {
            int col = wn + nt * 8 + t * 2;
            if (row < NN) {
                __half2 p = __floats2half2_rn(acc[mt][nt][0], acc[mt][nt][1]);
                *(uint32_t*)((char*)g_xwh + ((size_t)row * DH + col) * 2) =
                    *(uint32_t*)&p;
            }
            if (row + 8 < NN) {
                __half2 p = __floats2half2_rn(acc[mt][nt][2], acc[mt][nt][3]);
                *(uint32_t*)((char*)g_xwh + ((size_t)(row + 8) * DH + col) * 2) =
                    *(uint32_t*)&p;
            }
        }
    }
}

// ---------------- aggregation: h = relu( Ahat @ xw + b ) ----------------
// one warp per node, lane handles 4 cols (uint2, 8B); 2-edge unroll.
// Intermediate layers write h pre-split (bf16 hi/lo); last layer fuses FC.
__global__ __launch_bounds__(256) void k_agg(const float* __restrict__ b,
                                             const float* __restrict__ Wfc,
                                             const float* __restrict__ bfc,
                                             float* __restrict__ out) {
    int warp = (blockIdx.x * blockDim.x + threadIdx.x) >> 5;
    int lane = threadIdx.x & 31;
    if (warp >= NN) return;
    int node = warp;

    const uint2* xw = (const uint2*)g_xwh;   // 4 halves per uint2

    float dv   = g_dinv[node];
    float self = dv * dv;

    uint2 sraw = xw[node * 32 + lane];
    float2 f01 = __half22float2(*(__half2*)&sraw.x);
    float2 f23 = __half22float2(*(__half2*)&sraw.y);
    float4 acc = make_float4(f01.x * self, f01.y * self,
                             f23.x * self, f23.y * self);

    int start = g_off[node];
    int m     = g_cnt[node];

    int j = 0;
    for (; j + 1 < m; j += 2) {
        int2 e0 = g_edge[start + j];
        int2 e1 = g_edge[start + j + 1];
        uint2 r0 = xw[(size_t)e0.x * 32 + lane];
        uint2 r1 = xw[(size_t)e1.x * 32 + lane];
        float n0 = __int_as_float(e0.y);
        float n1 = __int_as_float(e1.y);
        float2 a01 = __half22float2(*(__half2*)&r0.x);
        float2 a23 = __half22float2(*(__half2*)&r0.y);
        float2 b01 = __half22float2(*(__half2*)&r1.x);
        float2 b23 = __half22float2(*(__half2*)&r1.y);
        acc.x += a01.x * n0 + b01.x * n1;
        acc.y += a01.y * n0 + b01.y * n1;
        acc.z += a23.x * n0 + b23.x * n1;
        acc.w += a23.y * n0 + b23.y * n1;
    }
    if (j < m) {
        int2 e0 = g_edge[start + j];
        uint2 r0 = xw[(size_t)e0.x * 32 + lane];
        float n0 = __int_as_float(e0.y);
        float2 a01 = __half22float2(*(__half2*)&r0.x);
        float2 a23 = __half22float2(*(__half2*)&r0.y);
        acc.x += a01.x * n0;
        acc.y += a01.y * n0;
        acc.z += a23.x * n0;
        acc.w += a23.y * n0;
    }

    float4 bb = ((const float4*)b)[lane];
    acc.x = fmaxf(acc.x + bb.x, 0.0f);
    acc.y = fmaxf(acc.y + bb.y, 0.0f);
    acc.z = fmaxf(acc.z + bb.z, 0.0f);
    acc.w = fmaxf(acc.w + bb.w, 0.0f);

    if (Wfc) {
        float4 w = ((const float4*)Wfc)[lane];
        float sum = acc.x * w.x + acc.y * w.y + acc.z * w.z + acc.w * w.w;
        #pragma unroll
        for (int d = 16; d > 0; d >>= 1)
            sum += __shfl_xor_sync(0xFFFFFFFFu, sum, d);
        if (lane == 0) out[node] = sum + bfc[0];
    } else {
        // emit h pre-split as bf16 hi/lo
        float rx, ry, rz, rw, z;
        uint32_t hx = bsplit_hi(acc.x, rx), hy = bsplit_hi(acc.y, ry);
        uint32_t hz = bsplit_hi(acc.z, rz), hw = bsplit_hi(acc.w, rw);
        uint32_t lx = bsplit_hi(rx, z), ly = bsplit_hi(ry, z);
        uint32_t lz = bsplit_hi(rz, z), lw = bsplit_hi(rw, z);
        ((uint2*)g_ah)[node * 32 + lane] =
            make_uint2(hx | (hy << 16), hz | (hw << 16));
        ((uint2*)g_al)[node * 32 + lane] =
            make_uint2(lx | (ly << 16), lz | (lw << 16));
    }
}

// ---------------- launch -------------------------------------------------
extern "C" void kernel_launch(void* const* d_in, const int* in_sizes, int n_in,
                              void* d_out, int out_size) {
    const float* x    = (const float*)d_in[0];
    const void*  ei   = d_in[1];
    const float* W1   = (const float*)d_in[2];
    const float* b1   = (const float*)d_in[3];
    const float* W2   = (const float*)d_in[4];
    const float* b2   = (const float*)d_in[5];
    const float* W3   = (const float*)d_in[6];
    const float* b3   = (const float*)d_in[7];
    const float* Wfc  = (const float*)d_in[8];
    const float* bfc  = (const float*)d_in[9];
    float* out = (float*)d_out;

    static int smem_set = 0;
    if (!smem_set) {
        cudaFuncSetAttribute(k_gemm_mma,
                             cudaFuncAttributeMaxDynamicSharedMemorySize,
                             SM2_TOTAL);
        smem_set = 1;
    }

    const int TB = 256;
    int ge = (EE + TB - 1) / TB;
    int gn = (NN + TB - 1) / TB;
    int gsx = (NN * DH / 4 + TB - 1) / TB;
    int ggemm = (NN + 127) / 128;
    int gwarp = (NN * 32 + TB - 1) / TB;

    k_splitx<<<gsx, TB>>>(x);                                // 1
    dim3 wgrid(DH, 3);
    k_wprep3<<<wgrid, DH>>>(W1, W2, W3);                     // 2
    k_dz<<<gn, TB>>>(ei);                                    // 3
    k_gemm_mma<<<ggemm, 256, SM2_TOTAL>>>(0);                // 4 <- profiled
    k_convert_count<<<ge, TB>>>(ei);                         // 5
    k_scan<<<1, 1024>>>();                                   // 6
    k_scatter<<<ge, TB>>>();                                 // 7
    k_agg<<<gwarp, TB>>>(b1, nullptr, nullptr, nullptr);     // 8
    k_gemm_mma<<<ggemm, 256, SM2_TOTAL>>>(1);                // 9
    k_agg<<<gwarp, TB>>>(b2, nullptr, nullptr, nullptr);     // 10
    k_gemm_mma<<<ggemm, 256, SM2_TOTAL>>>(2);                // 11
    k_agg<<<gwarp, TB>>>(b3, Wfc, bfc, out);                 // 12
}